// round 1
// baseline (speedup 1.0000x reference)
#include <cuda_runtime.h>
#include <math.h>

// ---------------------------------------------------------------------------
// Swin3D ViT block, fp32 baseline.
// B=2, H=32, W=32, D=16, C=384, HEADS=12, hd=32, window 4x4x4 (L=64), NOISE=256
// Tokens = 32768 (16384 per batch). All fp32.
// ---------------------------------------------------------------------------

#define TOK      32768
#define TOKB     16384   // tokens per batch
#define C_       384
#define SIXC     2304
#define NOISE_   256
#define HEADS_   12
#define HD_      32
#define LWIN     64
#define NWIN     512     // 2 * 8 * 8 * 4
#define EPS_     1e-5f

// scratch (device globals; allocation-free)
__device__ float g_params[2 * SIXC];            // AdaLN params [B, 6C]
__device__ float g_xmod[TOK * C_];              // LN+mod output
__device__ float g_qkv[TOK * 3 * C_];           // QKV
__device__ float g_attn[TOK * C_];              // attention output
__device__ float g_x1[TOK * C_];                // residual after attention
__device__ float g_h[TOK * 4 * C_];             // MLP hidden

// ---------------------------------------------------------------------------
// AdaLN params: params[b, j] = sum_i silu(x_noise[b,i]) * ada_w[j,i] + ada_b[j]
// grid = 2 * 9 blocks of 256
// ---------------------------------------------------------------------------
__global__ __launch_bounds__(256) void ada_kernel(
    const float* __restrict__ xn, const float* __restrict__ aw,
    const float* __restrict__ ab)
{
    __shared__ float s[NOISE_];
    int b  = blockIdx.x / 9;
    int jb = blockIdx.x % 9;
    float v = xn[b * NOISE_ + threadIdx.x];
    s[threadIdx.x] = v / (1.f + expf(-v));
    __syncthreads();
    int j = jb * 256 + threadIdx.x;
    const float* w = aw + (size_t)j * NOISE_;
    float acc = ab[j];
#pragma unroll 8
    for (int i = 0; i < NOISE_; i++) acc += w[i] * s[i];
    g_params[b * SIXC + j] = acc;
}

// ---------------------------------------------------------------------------
// LN (no affine) + AdaLN modulate. One warp per token, 8 tokens per block.
// out[tok,c] = ((x-mean)*rstd) * (1 + scale[b,c]) + shift[b,c]
// ---------------------------------------------------------------------------
__global__ __launch_bounds__(256) void ln_mod_kernel(
    const float* __restrict__ x, int shiftOff, int scaleOff,
    float* __restrict__ out)
{
    int warp = threadIdx.x >> 5, lane = threadIdx.x & 31;
    int tok = blockIdx.x * 8 + warp;
    int b = tok >> 14;
    const float* xr = x + (size_t)tok * C_;
    float v[12];
    float s = 0.f;
#pragma unroll
    for (int i = 0; i < 12; i++) { v[i] = xr[lane + 32 * i]; s += v[i]; }
#pragma unroll
    for (int o = 16; o; o >>= 1) s += __shfl_xor_sync(0xffffffffu, s, o);
    float mean = s * (1.f / 384.f);
    float sq = 0.f;
#pragma unroll
    for (int i = 0; i < 12; i++) { float d = v[i] - mean; sq += d * d; }
#pragma unroll
    for (int o = 16; o; o >>= 1) sq += __shfl_xor_sync(0xffffffffu, sq, o);
    float rstd = rsqrtf(sq * (1.f / 384.f) + EPS_);
    const float* sh = g_params + b * SIXC + shiftOff;
    const float* sc = g_params + b * SIXC + scaleOff;
    float* orow = out + (size_t)tok * C_;
#pragma unroll
    for (int i = 0; i < 12; i++) {
        int c = lane + 32 * i;
        orow[c] = (v[i] - mean) * rstd * (1.f + sc[c]) + sh[c];
    }
}

// ---------------------------------------------------------------------------
// SGEMM: C[M,N] = A[M,K] @ B[N,K]^T (+bias), optional fused epilogue.
// Block tile 128x128, BK=8, 256 threads, 8x8 per thread.
// M % 128 == 0, N % 128 == 0, K % 8 == 0 (holds for all our shapes).
// MODE 0: C = acc + bias
// MODE 1: C = gelu_exact(acc + bias)
// MODE 2: C = res + gate[b, gateOff + col] * (acc + bias)
// ---------------------------------------------------------------------------
template <int MODE>
__global__ __launch_bounds__(256) void gemm_kernel(
    const float* __restrict__ A, const float* __restrict__ Bw,
    const float* __restrict__ bias, float* __restrict__ Cout,
    int M, int N, int K,
    const float* __restrict__ res, int gateOff)
{
    __shared__ float As[8][128];
    __shared__ float Bs[8][128];

    int tid = threadIdx.x;
    int bm = blockIdx.y * 128;
    int bn = blockIdx.x * 128;
    int ty = tid / 16, tx = tid % 16;

    float acc[8][8];
#pragma unroll
    for (int i = 0; i < 8; i++)
#pragma unroll
        for (int j = 0; j < 8; j++) acc[i][j] = 0.f;

    int arow = tid >> 1;          // 0..127
    int acol = (tid & 1) * 4;     // 0 or 4
    const float* Ap = A + (size_t)(bm + arow) * K + acol;
    const float* Bp = Bw + (size_t)(bn + arow) * K + acol;

    for (int k0 = 0; k0 < K; k0 += 8) {
        float4 av = *(const float4*)(Ap + k0);
        float4 bv = *(const float4*)(Bp + k0);
        As[acol + 0][arow] = av.x;
        As[acol + 1][arow] = av.y;
        As[acol + 2][arow] = av.z;
        As[acol + 3][arow] = av.w;
        Bs[acol + 0][arow] = bv.x;
        Bs[acol + 1][arow] = bv.y;
        Bs[acol + 2][arow] = bv.z;
        Bs[acol + 3][arow] = bv.w;
        __syncthreads();
#pragma unroll
        for (int k = 0; k < 8; k++) {
            float a[8], b[8];
#pragma unroll
            for (int i = 0; i < 8; i++) a[i] = As[k][ty * 8 + i];
#pragma unroll
            for (int j = 0; j < 8; j++) b[j] = Bs[k][tx * 8 + j];
#pragma unroll
            for (int i = 0; i < 8; i++)
#pragma unroll
                for (int j = 0; j < 8; j++) acc[i][j] += a[i] * b[j];
        }
        __syncthreads();
    }

#pragma unroll
    for (int i = 0; i < 8; i++) {
        int row = bm + ty * 8 + i;
#pragma unroll
        for (int j = 0; j < 8; j++) {
            int col = bn + tx * 8 + j;
            float v = acc[i][j] + bias[col];
            if (MODE == 1) {
                v = 0.5f * v * (1.f + erff(v * 0.7071067811865476f));
            }
            if (MODE == 2) {
                int b = row >> 14;
                float g = g_params[b * SIXC + gateOff + col];
                v = res[(size_t)row * N + col] + g * v;
            }
            Cout[(size_t)row * N + col] = v;
        }
    }
}

// ---------------------------------------------------------------------------
// Windowed attention. One block per (window, head): 512*12 = 6144 blocks,
// 64 threads (one per query row of the window).
// ---------------------------------------------------------------------------
__global__ __launch_bounds__(64) void attn_kernel(
    const float* __restrict__ qkv, float* __restrict__ attn_out)
{
    __shared__ float ks[LWIN][HD_];
    __shared__ float vs[LWIN][HD_];

    int l = threadIdx.x;
    int win  = blockIdx.x / HEADS_;
    int head = blockIdx.x % HEADS_;

    // window -> (b, hb, wb, db) with shape (2, 8, 8, 4)
    int b   = win >> 8;
    int rem = win & 255;
    int hb  = rem >> 5;
    int rem2 = rem & 31;
    int wb  = rem2 >> 2;
    int db  = rem2 & 3;

    // row l -> (i, j, m) within window
    int i = l >> 4, j = (l >> 2) & 3, m = l & 3;
    int hh = hb * 4 + i, ww = wb * 4 + j, dd = db * 4 + m;
    size_t tok = (((size_t)(b * 32 + hh) * 32 + ww) * 16 + dd);

    const float* base = qkv + tok * (3 * C_) + head * HD_;
    float q[HD_];
#pragma unroll
    for (int t = 0; t < HD_; t++) {
        q[t]     = base[t];
        ks[l][t] = base[C_ + t];
        vs[l][t] = base[2 * C_ + t];
    }
    __syncthreads();

    float sc[LWIN];
    float mx = -1e30f;
#pragma unroll 4
    for (int r = 0; r < LWIN; r++) {
        float s = 0.f;
#pragma unroll
        for (int t = 0; t < HD_; t++) s += q[t] * ks[r][t];
        s *= 0.17677669529663687f;  // 1/sqrt(32)
        sc[r] = s;
        mx = fmaxf(mx, s);
    }
    float sum = 0.f;
#pragma unroll 4
    for (int r = 0; r < LWIN; r++) { sc[r] = expf(sc[r] - mx); sum += sc[r]; }
    float inv = 1.f / sum;

    float o[HD_];
#pragma unroll
    for (int t = 0; t < HD_; t++) o[t] = 0.f;
#pragma unroll 4
    for (int r = 0; r < LWIN; r++) {
        float p = sc[r] * inv;
#pragma unroll
        for (int t = 0; t < HD_; t++) o[t] += p * vs[r][t];
    }

    float* op = attn_out + tok * C_ + head * HD_;
#pragma unroll
    for (int t = 0; t < HD_; t++) op[t] = o[t];
}

// ---------------------------------------------------------------------------
// launch
// ---------------------------------------------------------------------------
extern "C" void kernel_launch(void* const* d_in, const int* in_sizes, int n_in,
                              void* d_out, int out_size)
{
    const float* x      = (const float*)d_in[0];
    const float* xn     = (const float*)d_in[1];
    const float* ada_w  = (const float*)d_in[2];
    const float* ada_b  = (const float*)d_in[3];
    const float* qkv_w  = (const float*)d_in[4];
    const float* qkv_b  = (const float*)d_in[5];
    const float* out_w  = (const float*)d_in[6];
    const float* out_b  = (const float*)d_in[7];
    const float* mlp_w1 = (const float*)d_in[8];
    const float* mlp_b1 = (const float*)d_in[9];
    const float* mlp_w2 = (const float*)d_in[10];
    const float* mlp_b2 = (const float*)d_in[11];
    float* out = (float*)d_out;

    float *p_xmod, *p_qkv, *p_attn, *p_x1, *p_h;
    cudaGetSymbolAddress((void**)&p_xmod, g_xmod);
    cudaGetSymbolAddress((void**)&p_qkv,  g_qkv);
    cudaGetSymbolAddress((void**)&p_attn, g_attn);
    cudaGetSymbolAddress((void**)&p_x1,   g_x1);
    cudaGetSymbolAddress((void**)&p_h,    g_h);

    // 1. AdaLN params
    ada_kernel<<<18, 256>>>(xn, ada_w, ada_b);

    // 2. LN + mod (shift1 @ 0, scale1 @ C)
    ln_mod_kernel<<<TOK / 8, 256>>>(x, 0, C_, p_xmod);

    // 3. QKV GEMM: [32768,384] @ [1152,384]^T
    {
        dim3 grid((3 * C_) / 128, TOK / 128);
        gemm_kernel<0><<<grid, 256>>>(p_xmod, qkv_w, qkv_b, p_qkv,
                                      TOK, 3 * C_, C_, nullptr, 0);
    }

    // 4. window attention
    attn_kernel<<<NWIN * HEADS_, 64>>>(p_qkv, p_attn);

    // 5. out proj + gate1 + residual -> x1
    {
        dim3 grid(C_ / 128, TOK / 128);
        gemm_kernel<2><<<grid, 256>>>(p_attn, out_w, out_b, p_x1,
                                      TOK, C_, C_, x, 2 * C_);
    }

    // 6. LN + mod (shift2 @ 3C, scale2 @ 4C)
    ln_mod_kernel<<<TOK / 8, 256>>>(p_x1, 3 * C_, 4 * C_, p_xmod);

    // 7. MLP1 + exact GELU
    {
        dim3 grid((4 * C_) / 128, TOK / 128);
        gemm_kernel<1><<<grid, 256>>>(p_xmod, mlp_w1, mlp_b1, p_h,
                                      TOK, 4 * C_, C_, nullptr, 0);
    }

    // 8. MLP2 + gate2 + residual -> d_out
    {
        dim3 grid(C_ / 128, TOK / 128);
        gemm_kernel<2><<<grid, 256>>>(p_h, mlp_w2, mlp_b2, out,
                                      TOK, C_, 4 * C_, p_x1, 5 * C_);
    }
}

// round 2
// speedup vs baseline: 3.6800x; 3.6800x over previous
#include <cuda_runtime.h>
#include <math.h>
#include <stdint.h>

// ---------------------------------------------------------------------------
// Swin3D ViT block. tf32 tensor-core GEMMs (mma.sync m16n8k8) + fused epilogues.
// B=2, H=32, W=32, D=16, C=384, HEADS=12, hd=32, window 4x4x4 (L=64), NOISE=256
// ---------------------------------------------------------------------------

#define TOK      32768
#define C_       384
#define SIXC     2304
#define NOISE_   256
#define HEADS_   12
#define HD_      32
#define LWIN     64
#define NWIN     512
#define EPS_     1e-5f

// scratch
__device__ float g_params[2 * SIXC];
__device__ float g_xmod[TOK * C_];
__device__ float g_qkv[TOK * 3 * C_];
__device__ float g_attn[TOK * C_];
__device__ float g_x1[TOK * C_];
__device__ float g_h[TOK * 4 * C_];
// tf32-rounded weight copies
__device__ float g_wq[3 * C_ * C_];
__device__ float g_wo[C_ * C_];
__device__ float g_w1[4 * C_ * C_];
__device__ float g_w2[4 * C_ * C_];

// ---------------------------------------------------------------------------
// helpers
// ---------------------------------------------------------------------------
__device__ __forceinline__ float tf32r(float x) {
    uint32_t u;
    asm("cvt.rna.tf32.f32 %0, %1;" : "=r"(u) : "f"(x));
    return __uint_as_float(u);
}

__device__ __forceinline__ void mma8(float* d, const uint32_t* a, const uint32_t* b) {
    asm volatile(
        "mma.sync.aligned.m16n8k8.row.col.f32.tf32.tf32.f32 "
        "{%0,%1,%2,%3}, {%4,%5,%6,%7}, {%8,%9}, {%0,%1,%2,%3};"
        : "+f"(d[0]), "+f"(d[1]), "+f"(d[2]), "+f"(d[3])
        : "r"(a[0]), "r"(a[1]), "r"(a[2]), "r"(a[3]), "r"(b[0]), "r"(b[1]));
}

__device__ __forceinline__ void cp16(void* sptr, const void* gptr) {
    unsigned sa = (unsigned)__cvta_generic_to_shared(sptr);
    asm volatile("cp.async.ca.shared.global [%0], [%1], 16;" :: "r"(sa), "l"(gptr));
}

// ---------------------------------------------------------------------------
// weight rounding to tf32
// ---------------------------------------------------------------------------
__global__ __launch_bounds__(256) void round_kernel(
    const float* __restrict__ src, float* __restrict__ dst, int n)
{
    int i = blockIdx.x * 256 + threadIdx.x;
    if (i < n) dst[i] = tf32r(src[i]);
}

// ---------------------------------------------------------------------------
// AdaLN params
// ---------------------------------------------------------------------------
__global__ __launch_bounds__(256) void ada_kernel(
    const float* __restrict__ xn, const float* __restrict__ aw,
    const float* __restrict__ ab)
{
    __shared__ float s[NOISE_];
    int b  = blockIdx.x / 9;
    int jb = blockIdx.x % 9;
    float v = xn[b * NOISE_ + threadIdx.x];
    s[threadIdx.x] = v / (1.f + expf(-v));
    __syncthreads();
    int j = jb * 256 + threadIdx.x;
    const float* w = aw + (size_t)j * NOISE_;
    float acc = ab[j];
#pragma unroll 8
    for (int i = 0; i < NOISE_; i++) acc += w[i] * s[i];
    g_params[b * SIXC + j] = acc;
}

// ---------------------------------------------------------------------------
// LN + modulate, output rounded to tf32 (feeds GEMM A)
// ---------------------------------------------------------------------------
__global__ __launch_bounds__(256) void ln_mod_kernel(
    const float* __restrict__ x, int shiftOff, int scaleOff,
    float* __restrict__ out)
{
    int warp = threadIdx.x >> 5, lane = threadIdx.x & 31;
    int tok = blockIdx.x * 8 + warp;
    int b = tok >> 14;
    const float* xr = x + (size_t)tok * C_;
    float v[12];
    float s = 0.f;
#pragma unroll
    for (int i = 0; i < 12; i++) { v[i] = xr[lane + 32 * i]; s += v[i]; }
#pragma unroll
    for (int o = 16; o; o >>= 1) s += __shfl_xor_sync(0xffffffffu, s, o);
    float mean = s * (1.f / 384.f);
    float sq = 0.f;
#pragma unroll
    for (int i = 0; i < 12; i++) { float d = v[i] - mean; sq += d * d; }
#pragma unroll
    for (int o = 16; o; o >>= 1) sq += __shfl_xor_sync(0xffffffffu, sq, o);
    float rstd = rsqrtf(sq * (1.f / 384.f) + EPS_);
    const float* sh = g_params + b * SIXC + shiftOff;
    const float* sc = g_params + b * SIXC + scaleOff;
    float* orow = out + (size_t)tok * C_;
#pragma unroll
    for (int i = 0; i < 12; i++) {
        int c = lane + 32 * i;
        orow[c] = tf32r((v[i] - mean) * rstd * (1.f + sc[c]) + sh[c]);
    }
}

// ---------------------------------------------------------------------------
// tf32 tensor-core GEMM: C[M,N] = A[M,K] @ W[N,K]^T (+bias) + epilogue.
// Inputs A, W must already be tf32-rounded. Block 128x128, BK=32,
// 128 threads = 4 warps, each 64x64. Double-buffered cp.async.
// MODE 0: bias only (qkv)
// MODE 1: gelu(.+bias), output tf32-rounded (mlp hidden)
// MODE 2: res + gate*( . + bias)
// ---------------------------------------------------------------------------
#define ASOFF(buf, r, k) ((buf) * (128 * 36) + (r) * 36 + (k))
#define SMEM_FLOATS (2 * 2 * 128 * 36)

template <int MODE>
__global__ __launch_bounds__(128) void gemm_tc(
    const float* __restrict__ A, const float* __restrict__ Bw,
    const float* __restrict__ bias, float* __restrict__ Cout,
    int M, int N, int K,
    const float* __restrict__ res, int gateOff)
{
    extern __shared__ float sm[];
    float* As = sm;                       // [2][128][36]
    float* Bs = sm + 2 * 128 * 36;        // [2][128][36]
    const uint32_t* Asu = (const uint32_t*)As;
    const uint32_t* Bsu = (const uint32_t*)Bs;

    int tid  = threadIdx.x;
    int warp = tid >> 5, lane = tid & 31;
    int g = lane >> 2, c = lane & 3;
    int wm = (warp >> 1) * 64;
    int wn = (warp & 1) * 64;
    int bm = blockIdx.y * 128;
    int bn = blockIdx.x * 128;

    float acc[4][8][4];
#pragma unroll
    for (int i = 0; i < 4; i++)
#pragma unroll
        for (int j = 0; j < 8; j++)
#pragma unroll
            for (int t = 0; t < 4; t++) acc[i][j][t] = 0.f;

    int nk = K >> 5;

    // stage tile 0
#pragma unroll
    for (int i = 0; i < 8; i++) {
        int idx = tid + 128 * i;
        int row = idx >> 3, c4 = (idx & 7) << 2;
        cp16(&As[ASOFF(0, row, c4)], A  + (size_t)(bm + row) * K + c4);
        cp16(&Bs[ASOFF(0, row, c4)], Bw + (size_t)(bn + row) * K + c4);
    }
    asm volatile("cp.async.commit_group;");

    for (int kt = 0; kt < nk; kt++) {
        int buf = kt & 1;
        if (kt + 1 < nk) {
            int k0 = (kt + 1) << 5;
#pragma unroll
            for (int i = 0; i < 8; i++) {
                int idx = tid + 128 * i;
                int row = idx >> 3, c4 = (idx & 7) << 2;
                cp16(&As[ASOFF(buf ^ 1, row, c4)], A  + (size_t)(bm + row) * K + k0 + c4);
                cp16(&Bs[ASOFF(buf ^ 1, row, c4)], Bw + (size_t)(bn + row) * K + k0 + c4);
            }
            asm volatile("cp.async.commit_group;");
            asm volatile("cp.async.wait_group 1;");
        } else {
            asm volatile("cp.async.wait_group 0;");
        }
        __syncthreads();

#pragma unroll
        for (int ks = 0; ks < 4; ks++) {
            int kb = ks << 3;
            uint32_t af[4][4], bf[8][2];
#pragma unroll
            for (int mt = 0; mt < 4; mt++) {
                int r = wm + mt * 16;
                af[mt][0] = Asu[ASOFF(buf, r + g,     kb + c)];
                af[mt][1] = Asu[ASOFF(buf, r + g + 8, kb + c)];
                af[mt][2] = Asu[ASOFF(buf, r + g,     kb + c + 4)];
                af[mt][3] = Asu[ASOFF(buf, r + g + 8, kb + c + 4)];
            }
#pragma unroll
            for (int nt = 0; nt < 8; nt++) {
                int col = wn + nt * 8;
                bf[nt][0] = Bsu[ASOFF(buf, col + g, kb + c)];
                bf[nt][1] = Bsu[ASOFF(buf, col + g, kb + c + 4)];
            }
#pragma unroll
            for (int mt = 0; mt < 4; mt++)
#pragma unroll
                for (int nt = 0; nt < 8; nt++)
                    mma8(acc[mt][nt], af[mt], bf[nt]);
        }
        __syncthreads();
    }

    // epilogue
#pragma unroll
    for (int mt = 0; mt < 4; mt++) {
        int r0 = bm + wm + mt * 16 + g;
#pragma unroll
        for (int nt = 0; nt < 8; nt++) {
            int col = bn + wn + nt * 8 + (c << 1);
            float b0 = bias[col], b1 = bias[col + 1];
#pragma unroll
            for (int half = 0; half < 2; half++) {
                int row = r0 + half * 8;
                float v0 = acc[mt][nt][half * 2 + 0] + b0;
                float v1 = acc[mt][nt][half * 2 + 1] + b1;
                if (MODE == 1) {
                    v0 = tf32r(0.5f * v0 * (1.f + erff(v0 * 0.7071067811865476f)));
                    v1 = tf32r(0.5f * v1 * (1.f + erff(v1 * 0.7071067811865476f)));
                }
                if (MODE == 2) {
                    int bb = row >> 14;
                    float g0 = g_params[bb * SIXC + gateOff + col];
                    float g1 = g_params[bb * SIXC + gateOff + col + 1];
                    const float2 rr = *(const float2*)(res + (size_t)row * N + col);
                    v0 = rr.x + g0 * v0;
                    v1 = rr.y + g1 * v1;
                }
                float2 o = make_float2(v0, v1);
                *(float2*)(Cout + (size_t)row * N + col) = o;
            }
        }
    }
}

// ---------------------------------------------------------------------------
// Windowed attention. Block = (window, head), 64 threads.
// Coalesced smem staging, no score array, no max-pass (scores are O(1)),
// output tf32-rounded (feeds out-proj GEMM).
// ---------------------------------------------------------------------------
__global__ __launch_bounds__(64) void attn_kernel(
    const float* __restrict__ qkv, float* __restrict__ attn_out)
{
    __shared__ float4 qs[LWIN][8];
    __shared__ float4 ks[LWIN][8];
    __shared__ float4 vs[LWIN][8];

    int lane = threadIdx.x & 31, half = threadIdx.x >> 5;
    int win  = blockIdx.x / HEADS_;
    int head = blockIdx.x % HEADS_;

    int b   = win >> 8;
    int rem = win & 255;
    int hb  = rem >> 5;
    int rem2 = rem & 31;
    int wb  = rem2 >> 2;
    int db  = rem2 & 3;
    int baseH = hb * 4, baseW = wb * 4, baseD = db * 4;

    // coalesced load: each warp handles alternating rows, lane = element
    for (int r = half; r < LWIN; r += 2) {
        int i = r >> 4, j = (r >> 2) & 3, m = r & 3;
        size_t tok = (((size_t)(b * 32 + baseH + i) * 32 + baseW + j) * 16 + baseD + m);
        const float* p = qkv + tok * (3 * C_) + head * HD_;
        ((float*)&qs[r][0])[lane] = p[lane];
        ((float*)&ks[r][0])[lane] = p[C_ + lane];
        ((float*)&vs[r][0])[lane] = p[2 * C_ + lane];
    }
    __syncthreads();

    int l = threadIdx.x;
    float4 q[8];
#pragma unroll
    for (int i = 0; i < 8; i++) q[i] = qs[l][i];

    float4 o[8];
#pragma unroll
    for (int i = 0; i < 8; i++) o[i] = make_float4(0.f, 0.f, 0.f, 0.f);
    float sum = 0.f;

#pragma unroll 2
    for (int r = 0; r < LWIN; r++) {
        float s = 0.f;
#pragma unroll
        for (int i = 0; i < 8; i++) {
            float4 kk = ks[r][i];
            s += q[i].x * kk.x + q[i].y * kk.y + q[i].z * kk.z + q[i].w * kk.w;
        }
        float e = __expf(s * 0.17677669529663687f);
        sum += e;
#pragma unroll
        for (int i = 0; i < 8; i++) {
            float4 vv = vs[r][i];
            o[i].x += e * vv.x; o[i].y += e * vv.y;
            o[i].z += e * vv.z; o[i].w += e * vv.w;
        }
    }

    float inv = 1.f / sum;
#pragma unroll
    for (int i = 0; i < 8; i++) {
        o[i].x *= inv; o[i].y *= inv; o[i].z *= inv; o[i].w *= inv;
        qs[l][i] = o[i];
    }
    __syncthreads();

    // coalesced store
    for (int r = half; r < LWIN; r += 2) {
        int i = r >> 4, j = (r >> 2) & 3, m = r & 3;
        size_t tok = (((size_t)(b * 32 + baseH + i) * 32 + baseW + j) * 16 + baseD + m);
        float v = ((const float*)&qs[r][0])[lane];
        attn_out[tok * C_ + head * HD_ + lane] = tf32r(v);
    }
}

// ---------------------------------------------------------------------------
// launch
// ---------------------------------------------------------------------------
extern "C" void kernel_launch(void* const* d_in, const int* in_sizes, int n_in,
                              void* d_out, int out_size)
{
    const float* x      = (const float*)d_in[0];
    const float* xn     = (const float*)d_in[1];
    const float* ada_w  = (const float*)d_in[2];
    const float* ada_b  = (const float*)d_in[3];
    const float* qkv_w  = (const float*)d_in[4];
    const float* qkv_b  = (const float*)d_in[5];
    const float* out_w  = (const float*)d_in[6];
    const float* out_b  = (const float*)d_in[7];
    const float* mlp_w1 = (const float*)d_in[8];
    const float* mlp_b1 = (const float*)d_in[9];
    const float* mlp_w2 = (const float*)d_in[10];
    const float* mlp_b2 = (const float*)d_in[11];
    float* out = (float*)d_out;

    float *p_xmod, *p_qkv, *p_attn, *p_x1, *p_h, *p_wq, *p_wo, *p_w1, *p_w2;
    cudaGetSymbolAddress((void**)&p_xmod, g_xmod);
    cudaGetSymbolAddress((void**)&p_qkv,  g_qkv);
    cudaGetSymbolAddress((void**)&p_attn, g_attn);
    cudaGetSymbolAddress((void**)&p_x1,   g_x1);
    cudaGetSymbolAddress((void**)&p_h,    g_h);
    cudaGetSymbolAddress((void**)&p_wq,   g_wq);
    cudaGetSymbolAddress((void**)&p_wo,   g_wo);
    cudaGetSymbolAddress((void**)&p_w1,   g_w1);
    cudaGetSymbolAddress((void**)&p_w2,   g_w2);

    size_t smem = SMEM_FLOATS * sizeof(float);  // 73,728 B
    cudaFuncSetAttribute(gemm_tc<0>, cudaFuncAttributeMaxDynamicSharedMemorySize, (int)smem);
    cudaFuncSetAttribute(gemm_tc<1>, cudaFuncAttributeMaxDynamicSharedMemorySize, (int)smem);
    cudaFuncSetAttribute(gemm_tc<2>, cudaFuncAttributeMaxDynamicSharedMemorySize, (int)smem);

    // 0. round weights to tf32
    round_kernel<<<(3 * C_ * C_ + 255) / 256, 256>>>(qkv_w,  p_wq, 3 * C_ * C_);
    round_kernel<<<(C_ * C_ + 255) / 256, 256>>>(out_w,      p_wo, C_ * C_);
    round_kernel<<<(4 * C_ * C_ + 255) / 256, 256>>>(mlp_w1, p_w1, 4 * C_ * C_);
    round_kernel<<<(4 * C_ * C_ + 255) / 256, 256>>>(mlp_w2, p_w2, 4 * C_ * C_);

    // 1. AdaLN params
    ada_kernel<<<18, 256>>>(xn, ada_w, ada_b);

    // 2. LN + mod (shift1, scale1)
    ln_mod_kernel<<<TOK / 8, 256>>>(x, 0, C_, p_xmod);

    // 3. QKV GEMM
    {
        dim3 grid((3 * C_) / 128, TOK / 128);
        gemm_tc<0><<<grid, 128, smem>>>(p_xmod, p_wq, qkv_b, p_qkv,
                                        TOK, 3 * C_, C_, nullptr, 0);
    }

    // 4. window attention
    attn_kernel<<<NWIN * HEADS_, 64>>>(p_qkv, p_attn);

    // 5. out proj + gate1 + residual
    {
        dim3 grid(C_ / 128, TOK / 128);
        gemm_tc<2><<<grid, 128, smem>>>(p_attn, p_wo, out_b, p_x1,
                                        TOK, C_, C_, x, 2 * C_);
    }

    // 6. LN + mod (shift2, scale2)
    ln_mod_kernel<<<TOK / 8, 256>>>(p_x1, 3 * C_, 4 * C_, p_xmod);

    // 7. MLP1 + GELU
    {
        dim3 grid((4 * C_) / 128, TOK / 128);
        gemm_tc<1><<<grid, 128, smem>>>(p_xmod, p_w1, mlp_b1, p_h,
                                        TOK, 4 * C_, C_, nullptr, 0);
    }

    // 8. MLP2 + gate2 + residual
    {
        dim3 grid(C_ / 128, TOK / 128);
        gemm_tc<2><<<grid, 128, smem>>>(p_h, p_w2, mlp_b2, out,
                                        TOK, C_, 4 * C_, p_x1, 5 * C_);
    }
}

// round 3
// speedup vs baseline: 5.6891x; 1.5459x over previous
#include <cuda_runtime.h>
#include <cuda_bf16.h>
#include <math.h>
#include <stdint.h>

// ---------------------------------------------------------------------------
// Swin3D ViT block. bf16 tensor-core GEMMs (mma.sync m16n8k16) everywhere,
// fp32 residual stream. B=2, 32x32x16 tokens, C=384, 12 heads x hd=32,
// 4x4x4 windows (L=64), NOISE=256.
// ---------------------------------------------------------------------------

#define TOK      32768
#define C_       384
#define SIXC     2304
#define NOISE_   256
#define HEADS_   12
#define LWIN     64
#define NWIN     512
#define EPS_     1e-5f

// scratch
__device__ float g_params[2 * SIXC];
__device__ float g_x1[TOK * C_];                       // fp32 residual after attn
__device__ __nv_bfloat16 g_xmod[TOK * C_];             // LN+mod (bf16)
__device__ __nv_bfloat16 g_qkv[TOK * 3 * C_];          // QKV (bf16)
__device__ __nv_bfloat16 g_attn[TOK * C_];             // attention out (bf16)
__device__ __nv_bfloat16 g_h[TOK * 4 * C_];            // MLP hidden (bf16)
// bf16 weight copies
__device__ __nv_bfloat16 g_wq[3 * C_ * C_];
__device__ __nv_bfloat16 g_wo[C_ * C_];
__device__ __nv_bfloat16 g_w1[4 * C_ * C_];
__device__ __nv_bfloat16 g_w2[4 * C_ * C_];

// ---------------------------------------------------------------------------
__device__ __forceinline__ uint32_t packbf(float lo, float hi) {
    __nv_bfloat162 t = __floats2bfloat162_rn(lo, hi);  // .x = lo (low 16 bits)
    return *(uint32_t*)&t;
}

__device__ __forceinline__ void mmabf(float* d, const uint32_t* a, const uint32_t* b) {
    asm volatile(
        "mma.sync.aligned.m16n8k16.row.col.f32.bf16.bf16.f32 "
        "{%0,%1,%2,%3}, {%4,%5,%6,%7}, {%8,%9}, {%0,%1,%2,%3};"
        : "+f"(d[0]), "+f"(d[1]), "+f"(d[2]), "+f"(d[3])
        : "r"(a[0]), "r"(a[1]), "r"(a[2]), "r"(a[3]), "r"(b[0]), "r"(b[1]));
}

__device__ __forceinline__ void cp16(void* sptr, const void* gptr) {
    unsigned sa = (unsigned)__cvta_generic_to_shared(sptr);
    asm volatile("cp.async.ca.shared.global [%0], [%1], 16;" :: "r"(sa), "l"(gptr));
}

// ---------------------------------------------------------------------------
// weight conversion fp32 -> bf16 (all four weights, one kernel)
// ---------------------------------------------------------------------------
#define NWQ (3 * C_ * C_)
#define NWO (C_ * C_)
#define NW1 (4 * C_ * C_)
#define NW2 (4 * C_ * C_)
__global__ __launch_bounds__(256) void cvt_kernel(
    const float* __restrict__ wq, const float* __restrict__ wo,
    const float* __restrict__ w1, const float* __restrict__ w2)
{
    int i = blockIdx.x * 256 + threadIdx.x;
    if (i < NWQ) { g_wq[i] = __float2bfloat16(wq[i]); return; }
    i -= NWQ;
    if (i < NWO) { g_wo[i] = __float2bfloat16(wo[i]); return; }
    i -= NWO;
    if (i < NW1) { g_w1[i] = __float2bfloat16(w1[i]); return; }
    i -= NW1;
    if (i < NW2) { g_w2[i] = __float2bfloat16(w2[i]); }
}

// ---------------------------------------------------------------------------
// AdaLN params
// ---------------------------------------------------------------------------
__global__ __launch_bounds__(256) void ada_kernel(
    const float* __restrict__ xn, const float* __restrict__ aw,
    const float* __restrict__ ab)
{
    __shared__ float s[NOISE_];
    int b  = blockIdx.x / 9;
    int jb = blockIdx.x % 9;
    float v = xn[b * NOISE_ + threadIdx.x];
    s[threadIdx.x] = v / (1.f + expf(-v));
    __syncthreads();
    int j = jb * 256 + threadIdx.x;
    const float* w = aw + (size_t)j * NOISE_;
    float acc = ab[j];
#pragma unroll 8
    for (int i = 0; i < NOISE_; i++) acc += w[i] * s[i];
    g_params[b * SIXC + j] = acc;
}

// ---------------------------------------------------------------------------
// LN + modulate -> bf16 output. One warp per token.
// ---------------------------------------------------------------------------
__global__ __launch_bounds__(256) void ln_mod_kernel(
    const float* __restrict__ x, int shiftOff, int scaleOff,
    uint32_t* __restrict__ out)
{
    int warp = threadIdx.x >> 5, lane = threadIdx.x & 31;
    int tok = blockIdx.x * 8 + warp;
    int b = tok >> 14;
    const float4* xr = (const float4*)(x + (size_t)tok * C_);
    float4 v[3];
    float s = 0.f;
#pragma unroll
    for (int i = 0; i < 3; i++) {
        v[i] = xr[lane + 32 * i];
        s += v[i].x + v[i].y + v[i].z + v[i].w;
    }
#pragma unroll
    for (int o = 16; o; o >>= 1) s += __shfl_xor_sync(0xffffffffu, s, o);
    float mean = s * (1.f / 384.f);
    float sq = 0.f;
#pragma unroll
    for (int i = 0; i < 3; i++) {
        float dx = v[i].x - mean, dy = v[i].y - mean;
        float dz = v[i].z - mean, dw = v[i].w - mean;
        sq += dx * dx + dy * dy + dz * dz + dw * dw;
    }
#pragma unroll
    for (int o = 16; o; o >>= 1) sq += __shfl_xor_sync(0xffffffffu, sq, o);
    float rstd = rsqrtf(sq * (1.f / 384.f) + EPS_);
    const float4* sh4 = (const float4*)(g_params + b * SIXC + shiftOff);
    const float4* sc4 = (const float4*)(g_params + b * SIXC + scaleOff);
    uint32_t* orow = out + (size_t)tok * (C_ / 2);
#pragma unroll
    for (int i = 0; i < 3; i++) {
        int idx = lane + 32 * i;
        float4 s4 = sh4[idx], m4 = sc4[idx];
        float y0 = (v[i].x - mean) * rstd * (1.f + m4.x) + s4.x;
        float y1 = (v[i].y - mean) * rstd * (1.f + m4.y) + s4.y;
        float y2 = (v[i].z - mean) * rstd * (1.f + m4.z) + s4.z;
        float y3 = (v[i].w - mean) * rstd * (1.f + m4.w) + s4.w;
        orow[idx * 2]     = packbf(y0, y1);
        orow[idx * 2 + 1] = packbf(y2, y3);
    }
}

// ---------------------------------------------------------------------------
// bf16 tensor-core GEMM: C[M,N] = A[M,K] @ W[N,K]^T (+bias) + epilogue.
// A, W bf16 packed as u32 pairs (K2 = K/2 u32 per row). Block 128x128,
// BK=32 elements (16 u32), 128 threads = 4 warps, each 64x64. Double buffered.
// MODE 0: bias -> bf16 out (qkv)
// MODE 1: gelu(.+bias) -> bf16 out (mlp hidden)
// MODE 2: res + gate*(.+bias) -> fp32 out
// ---------------------------------------------------------------------------
#define SOFF(buf, r, k) ((buf) * (128 * 20) + (r) * 20 + (k))

template <int MODE>
__global__ __launch_bounds__(128) void gemm_bf(
    const uint32_t* __restrict__ A, const uint32_t* __restrict__ Bw,
    const float* __restrict__ bias, void* __restrict__ Cout,
    int M, int N, int K2,
    const float* __restrict__ res, int gateOff)
{
    __shared__ uint32_t As[2 * 128 * 20];
    __shared__ uint32_t Bs[2 * 128 * 20];

    int tid  = threadIdx.x;
    int warp = tid >> 5, lane = tid & 31;
    int g = lane >> 2, c = lane & 3;
    int wm = (warp >> 1) * 64;
    int wn = (warp & 1) * 64;
    int bm = blockIdx.y * 128;
    int bn = blockIdx.x * 128;

    float acc[4][8][4];
#pragma unroll
    for (int i = 0; i < 4; i++)
#pragma unroll
        for (int j = 0; j < 8; j++)
#pragma unroll
            for (int t = 0; t < 4; t++) acc[i][j][t] = 0.f;

    int nk = K2 >> 4;  // BK = 16 u32

    // stage tile 0
#pragma unroll
    for (int i = 0; i < 4; i++) {
        int idx = tid + 128 * i;
        int row = idx >> 2, c4 = (idx & 3) << 2;
        cp16(&As[SOFF(0, row, c4)], A  + (size_t)(bm + row) * K2 + c4);
        cp16(&Bs[SOFF(0, row, c4)], Bw + (size_t)(bn + row) * K2 + c4);
    }
    asm volatile("cp.async.commit_group;");

    for (int kt = 0; kt < nk; kt++) {
        int buf = kt & 1;
        if (kt + 1 < nk) {
            int k0 = (kt + 1) << 4;
#pragma unroll
            for (int i = 0; i < 4; i++) {
                int idx = tid + 128 * i;
                int row = idx >> 2, c4 = (idx & 3) << 2;
                cp16(&As[SOFF(buf ^ 1, row, c4)], A  + (size_t)(bm + row) * K2 + k0 + c4);
                cp16(&Bs[SOFF(buf ^ 1, row, c4)], Bw + (size_t)(bn + row) * K2 + k0 + c4);
            }
            asm volatile("cp.async.commit_group;");
            asm volatile("cp.async.wait_group 1;");
        } else {
            asm volatile("cp.async.wait_group 0;");
        }
        __syncthreads();

#pragma unroll
        for (int ks = 0; ks < 2; ks++) {   // two k16 steps per BK=32
            int kb = ks << 3;
            uint32_t af[4][4], bf[8][2];
#pragma unroll
            for (int mt = 0; mt < 4; mt++) {
                int r = wm + mt * 16;
                af[mt][0] = As[SOFF(buf, r + g,     kb + c)];
                af[mt][1] = As[SOFF(buf, r + g + 8, kb + c)];
                af[mt][2] = As[SOFF(buf, r + g,     kb + c + 4)];
                af[mt][3] = As[SOFF(buf, r + g + 8, kb + c + 4)];
            }
#pragma unroll
            for (int nt = 0; nt < 8; nt++) {
                int col = wn + nt * 8;
                bf[nt][0] = Bs[SOFF(buf, col + g, kb + c)];
                bf[nt][1] = Bs[SOFF(buf, col + g, kb + c + 4)];
            }
#pragma unroll
            for (int mt = 0; mt < 4; mt++)
#pragma unroll
                for (int nt = 0; nt < 8; nt++)
                    mmabf(acc[mt][nt], af[mt], bf[nt]);
        }
        __syncthreads();
    }

    // epilogue
#pragma unroll
    for (int mt = 0; mt < 4; mt++) {
        int r0 = bm + wm + mt * 16 + g;
#pragma unroll
        for (int nt = 0; nt < 8; nt++) {
            int col = bn + wn + nt * 8 + (c << 1);
            float b0 = bias[col], b1 = bias[col + 1];
#pragma unroll
            for (int half = 0; half < 2; half++) {
                int row = r0 + half * 8;
                float v0 = acc[mt][nt][half * 2 + 0] + b0;
                float v1 = acc[mt][nt][half * 2 + 1] + b1;
                if (MODE == 1) {
                    v0 = 0.5f * v0 * (1.f + erff(v0 * 0.7071067811865476f));
                    v1 = 0.5f * v1 * (1.f + erff(v1 * 0.7071067811865476f));
                }
                if (MODE == 2) {
                    int bb = row >> 14;
                    float g0 = g_params[bb * SIXC + gateOff + col];
                    float g1 = g_params[bb * SIXC + gateOff + col + 1];
                    const float2 rr = *(const float2*)(res + (size_t)row * N + col);
                    *(float2*)((float*)Cout + (size_t)row * N + col) =
                        make_float2(rr.x + g0 * v0, rr.y + g1 * v1);
                } else {
                    ((uint32_t*)Cout)[(size_t)row * (N >> 1) + (col >> 1)] = packbf(v0, v1);
                }
            }
        }
    }
}

// ---------------------------------------------------------------------------
// Windowed attention, bf16 tensor cores. Block = (window, head), 128 threads
// = 4 warps; warp w handles query rows [16w, 16w+16).
// ---------------------------------------------------------------------------
__global__ __launch_bounds__(128) void attn_kernel(
    const uint32_t* __restrict__ qkv, uint32_t* __restrict__ attn_out)
{
    __shared__ uint32_t Qs[64 * 20];
    __shared__ uint32_t Ks[64 * 20];
    __shared__ __nv_bfloat16 Vt[32 * 72];   // V transposed [hd][key], stride 72

    int tid = threadIdx.x;
    int warp = tid >> 5, lane = tid & 31;
    int g = lane >> 2, c = lane & 3;
    int win  = blockIdx.x / HEADS_;
    int head = blockIdx.x % HEADS_;

    int b = win >> 8, rem = win & 255;
    int hb = rem >> 5, rem2 = rem & 31, wb = rem2 >> 2, db = rem2 & 3;
    int base = b * 16384 + hb * 4 * 512 + wb * 4 * 16 + db * 4;
    // row r -> token: base + (r>>4)*512 + ((r>>2)&3)*16 + (r&3)

    // Q, K: 64 rows x 16 u32 (hd = 32 bf16)
    for (int idx = tid; idx < 1024; idx += 128) {
        int r = idx >> 4, cc = idx & 15;
        int tok = base + (r >> 4) * 512 + ((r >> 2) & 3) * 16 + (r & 3);
        const uint32_t* p = qkv + (size_t)tok * 576 + head * 16 + cc;
        Qs[r * 20 + cc] = p[0];
        Ks[r * 20 + cc] = p[192];
    }
    // V transposed
    const __nv_bfloat16* qkvh = (const __nv_bfloat16*)qkv;
    for (int idx = tid; idx < 2048; idx += 128) {
        int r = idx >> 5, hd = idx & 31;
        int tok = base + (r >> 4) * 512 + ((r >> 2) & 3) * 16 + (r & 3);
        Vt[hd * 72 + r] = qkvh[(size_t)tok * 1152 + 768 + head * 32 + hd];
    }
    __syncthreads();

    // S = Q @ K^T for this warp's 16 q rows (8 n-tiles of 8 keys)
    float sacc[8][4];
#pragma unroll
    for (int i = 0; i < 8; i++)
#pragma unroll
        for (int t = 0; t < 4; t++) sacc[i][t] = 0.f;

    int r0 = warp * 16;
#pragma unroll
    for (int ks = 0; ks < 2; ks++) {
        int kb = ks << 3;
        uint32_t af[4];
        af[0] = Qs[(r0 + g) * 20 + kb + c];
        af[1] = Qs[(r0 + g + 8) * 20 + kb + c];
        af[2] = Qs[(r0 + g) * 20 + kb + c + 4];
        af[3] = Qs[(r0 + g + 8) * 20 + kb + c + 4];
#pragma unroll
        for (int nt = 0; nt < 8; nt++) {
            uint32_t bf[2];
            bf[0] = Ks[(nt * 8 + g) * 20 + kb + c];
            bf[1] = Ks[(nt * 8 + g) * 20 + kb + c + 4];
            mmabf(sacc[nt], af, bf);
        }
    }

    // softmax (fp32, no max-pass; scores O(1))
    const float SC = 0.17677669529663687f;
    float slo = 0.f, shi = 0.f;
#pragma unroll
    for (int nt = 0; nt < 8; nt++) {
        sacc[nt][0] = __expf(sacc[nt][0] * SC);
        sacc[nt][1] = __expf(sacc[nt][1] * SC);
        sacc[nt][2] = __expf(sacc[nt][2] * SC);
        sacc[nt][3] = __expf(sacc[nt][3] * SC);
        slo += sacc[nt][0] + sacc[nt][1];
        shi += sacc[nt][2] + sacc[nt][3];
    }
    slo += __shfl_xor_sync(0xffffffffu, slo, 1);
    slo += __shfl_xor_sync(0xffffffffu, slo, 2);
    shi += __shfl_xor_sync(0xffffffffu, shi, 1);
    shi += __shfl_xor_sync(0xffffffffu, shi, 2);

    // O = P @ V  (P unnormalized exp, bf16; V^T in smem)
    float o[4][4];
#pragma unroll
    for (int i = 0; i < 4; i++)
#pragma unroll
        for (int t = 0; t < 4; t++) o[i][t] = 0.f;

    const uint32_t* Vt32 = (const uint32_t*)Vt;
#pragma unroll
    for (int kt = 0; kt < 4; kt++) {
        uint32_t pa[4];
        pa[0] = packbf(sacc[2 * kt][0],     sacc[2 * kt][1]);
        pa[1] = packbf(sacc[2 * kt][2],     sacc[2 * kt][3]);
        pa[2] = packbf(sacc[2 * kt + 1][0], sacc[2 * kt + 1][1]);
        pa[3] = packbf(sacc[2 * kt + 1][2], sacc[2 * kt + 1][3]);
#pragma unroll
        for (int nt = 0; nt < 4; nt++) {
            uint32_t bf[2];
            const uint32_t* vrow = Vt32 + (nt * 8 + g) * 36;
            bf[0] = vrow[kt * 8 + c];
            bf[1] = vrow[kt * 8 + c + 4];
            mmabf(o[nt], pa, bf);
        }
    }

    float inv_lo = 1.f / slo, inv_hi = 1.f / shi;
#pragma unroll
    for (int half = 0; half < 2; half++) {
        int r = r0 + g + half * 8;
        int tok = base + (r >> 4) * 512 + ((r >> 2) & 3) * 16 + (r & 3);
        uint32_t* op = attn_out + (size_t)tok * 192 + head * 16;
        float inv = half ? inv_hi : inv_lo;
#pragma unroll
        for (int nt = 0; nt < 4; nt++)
            op[nt * 4 + c] = packbf(o[nt][half * 2] * inv, o[nt][half * 2 + 1] * inv);
    }
}

// ---------------------------------------------------------------------------
// launch
// ---------------------------------------------------------------------------
extern "C" void kernel_launch(void* const* d_in, const int* in_sizes, int n_in,
                              void* d_out, int out_size)
{
    const float* x      = (const float*)d_in[0];
    const float* xn     = (const float*)d_in[1];
    const float* ada_w  = (const float*)d_in[2];
    const float* ada_b  = (const float*)d_in[3];
    const float* qkv_w  = (const float*)d_in[4];
    const float* qkv_b  = (const float*)d_in[5];
    const float* out_w  = (const float*)d_in[6];
    const float* out_b  = (const float*)d_in[7];
    const float* mlp_w1 = (const float*)d_in[8];
    const float* mlp_b1 = (const float*)d_in[9];
    const float* mlp_w2 = (const float*)d_in[10];
    const float* mlp_b2 = (const float*)d_in[11];
    float* out = (float*)d_out;

    void *p_xmod, *p_qkv, *p_attn, *p_x1, *p_h, *p_wq, *p_wo, *p_w1, *p_w2;
    cudaGetSymbolAddress(&p_xmod, g_xmod);
    cudaGetSymbolAddress(&p_qkv,  g_qkv);
    cudaGetSymbolAddress(&p_attn, g_attn);
    cudaGetSymbolAddress(&p_x1,   g_x1);
    cudaGetSymbolAddress(&p_h,    g_h);
    cudaGetSymbolAddress(&p_wq,   g_wq);
    cudaGetSymbolAddress(&p_wo,   g_wo);
    cudaGetSymbolAddress(&p_w1,   g_w1);
    cudaGetSymbolAddress(&p_w2,   g_w2);

    // 0. convert weights to bf16 (one kernel)
    cvt_kernel<<<(NWQ + NWO + NW1 + NW2) / 256, 256>>>(qkv_w, out_w, mlp_w1, mlp_w2);

    // 1. AdaLN params
    ada_kernel<<<18, 256>>>(xn, ada_w, ada_b);

    // 2. LN + mod (shift1, scale1) -> bf16
    ln_mod_kernel<<<TOK / 8, 256>>>(x, 0, C_, (uint32_t*)p_xmod);

    // 3. QKV GEMM -> bf16
    {
        dim3 grid((3 * C_) / 128, TOK / 128);
        gemm_bf<0><<<grid, 128>>>((const uint32_t*)p_xmod, (const uint32_t*)p_wq,
                                  qkv_b, p_qkv, TOK, 3 * C_, C_ / 2, nullptr, 0);
    }

    // 4. window attention (bf16 mma) -> bf16
    attn_kernel<<<NWIN * HEADS_, 128>>>((const uint32_t*)p_qkv, (uint32_t*)p_attn);

    // 5. out proj + gate1 + residual -> fp32 x1
    {
        dim3 grid(C_ / 128, TOK / 128);
        gemm_bf<2><<<grid, 128>>>((const uint32_t*)p_attn, (const uint32_t*)p_wo,
                                  out_b, p_x1, TOK, C_, C_ / 2, x, 2 * C_);
    }

    // 6. LN + mod (shift2, scale2) -> bf16
    ln_mod_kernel<<<TOK / 8, 256>>>((const float*)p_x1, 3 * C_, 4 * C_, (uint32_t*)p_xmod);

    // 7. MLP1 + GELU -> bf16
    {
        dim3 grid((4 * C_) / 128, TOK / 128);
        gemm_bf<1><<<grid, 128>>>((const uint32_t*)p_xmod, (const uint32_t*)p_w1,
                                  mlp_b1, p_h, TOK, 4 * C_, C_ / 2, nullptr, 0);
    }

    // 8. MLP2 + gate2 + residual -> fp32 out
    {
        dim3 grid(C_ / 128, TOK / 128);
        gemm_bf<2><<<grid, 128>>>((const uint32_t*)p_h, (const uint32_t*)p_w2,
                                  mlp_b2, out, TOK, C_, 2 * C_, (const float*)p_x1, 5 * C_);
    }
}

// round 4
// speedup vs baseline: 5.8965x; 1.0365x over previous
#include <cuda_runtime.h>
#include <cuda_bf16.h>
#include <math.h>
#include <stdint.h>

// ---------------------------------------------------------------------------
// Swin3D ViT block. bf16 mma.sync GEMMs, 8-warp blocks, ldmatrix fragments.
// ---------------------------------------------------------------------------

#define TOK      32768
#define C_       384
#define SIXC     2304
#define NOISE_   256
#define HEADS_   12
#define LWIN     64
#define NWIN     512
#define EPS_     1e-5f

// scratch
__device__ float g_params[2 * SIXC];
__device__ float g_x1[TOK * C_];
__device__ __nv_bfloat16 g_xmod[TOK * C_];
__device__ __nv_bfloat16 g_qkv[TOK * 3 * C_];
__device__ __nv_bfloat16 g_attn[TOK * C_];
__device__ __nv_bfloat16 g_h[TOK * 4 * C_];
__device__ __nv_bfloat16 g_wq[3 * C_ * C_];
__device__ __nv_bfloat16 g_wo[C_ * C_];
__device__ __nv_bfloat16 g_w1[4 * C_ * C_];
__device__ __nv_bfloat16 g_w2[4 * C_ * C_];

// ---------------------------------------------------------------------------
__device__ __forceinline__ uint32_t packbf(float lo, float hi) {
    __nv_bfloat162 t = __floats2bfloat162_rn(lo, hi);
    return *(uint32_t*)&t;
}

__device__ __forceinline__ void mmabf(float* d, const uint32_t* a, const uint32_t* b) {
    asm volatile(
        "mma.sync.aligned.m16n8k16.row.col.f32.bf16.bf16.f32 "
        "{%0,%1,%2,%3}, {%4,%5,%6,%7}, {%8,%9}, {%0,%1,%2,%3};"
        : "+f"(d[0]), "+f"(d[1]), "+f"(d[2]), "+f"(d[3])
        : "r"(a[0]), "r"(a[1]), "r"(a[2]), "r"(a[3]), "r"(b[0]), "r"(b[1]));
}

__device__ __forceinline__ void ldsm4(uint32_t* r, const uint32_t* sptr) {
    uint32_t a = (uint32_t)__cvta_generic_to_shared(sptr);
    asm volatile("ldmatrix.sync.aligned.m8n8.x4.shared.b16 {%0,%1,%2,%3}, [%4];"
                 : "=r"(r[0]), "=r"(r[1]), "=r"(r[2]), "=r"(r[3]) : "r"(a));
}

__device__ __forceinline__ void cp16(void* sptr, const void* gptr) {
    unsigned sa = (unsigned)__cvta_generic_to_shared(sptr);
    asm volatile("cp.async.ca.shared.global [%0], [%1], 16;" :: "r"(sa), "l"(gptr));
}

// ---------------------------------------------------------------------------
// weight conversion
// ---------------------------------------------------------------------------
#define NWQ (3 * C_ * C_)
#define NWO (C_ * C_)
#define NW1 (4 * C_ * C_)
#define NW2 (4 * C_ * C_)
__global__ __launch_bounds__(256) void cvt_kernel(
    const float* __restrict__ wq, const float* __restrict__ wo,
    const float* __restrict__ w1, const float* __restrict__ w2)
{
    int i = blockIdx.x * 256 + threadIdx.x;
    if (i < NWQ) { g_wq[i] = __float2bfloat16(wq[i]); return; }
    i -= NWQ;
    if (i < NWO) { g_wo[i] = __float2bfloat16(wo[i]); return; }
    i -= NWO;
    if (i < NW1) { g_w1[i] = __float2bfloat16(w1[i]); return; }
    i -= NW1;
    if (i < NW2) { g_w2[i] = __float2bfloat16(w2[i]); }
}

// ---------------------------------------------------------------------------
// AdaLN params
// ---------------------------------------------------------------------------
__global__ __launch_bounds__(256) void ada_kernel(
    const float* __restrict__ xn, const float* __restrict__ aw,
    const float* __restrict__ ab)
{
    __shared__ float s[NOISE_];
    int b  = blockIdx.x / 9;
    int jb = blockIdx.x % 9;
    float v = xn[b * NOISE_ + threadIdx.x];
    s[threadIdx.x] = v / (1.f + expf(-v));
    __syncthreads();
    int j = jb * 256 + threadIdx.x;
    const float* w = aw + (size_t)j * NOISE_;
    float acc = ab[j];
#pragma unroll 8
    for (int i = 0; i < NOISE_; i++) acc += w[i] * s[i];
    g_params[b * SIXC + j] = acc;
}

// ---------------------------------------------------------------------------
// LN + modulate -> bf16
// ---------------------------------------------------------------------------
__global__ __launch_bounds__(256) void ln_mod_kernel(
    const float* __restrict__ x, int shiftOff, int scaleOff,
    uint32_t* __restrict__ out)
{
    int warp = threadIdx.x >> 5, lane = threadIdx.x & 31;
    int tok = blockIdx.x * 8 + warp;
    int b = tok >> 14;
    const float4* xr = (const float4*)(x + (size_t)tok * C_);
    float4 v[3];
    float s = 0.f;
#pragma unroll
    for (int i = 0; i < 3; i++) {
        v[i] = xr[lane + 32 * i];
        s += v[i].x + v[i].y + v[i].z + v[i].w;
    }
#pragma unroll
    for (int o = 16; o; o >>= 1) s += __shfl_xor_sync(0xffffffffu, s, o);
    float mean = s * (1.f / 384.f);
    float sq = 0.f;
#pragma unroll
    for (int i = 0; i < 3; i++) {
        float dx = v[i].x - mean, dy = v[i].y - mean;
        float dz = v[i].z - mean, dw = v[i].w - mean;
        sq += dx * dx + dy * dy + dz * dz + dw * dw;
    }
#pragma unroll
    for (int o = 16; o; o >>= 1) sq += __shfl_xor_sync(0xffffffffu, sq, o);
    float rstd = rsqrtf(sq * (1.f / 384.f) + EPS_);
    const float4* sh4 = (const float4*)(g_params + b * SIXC + shiftOff);
    const float4* sc4 = (const float4*)(g_params + b * SIXC + scaleOff);
    uint32_t* orow = out + (size_t)tok * (C_ / 2);
#pragma unroll
    for (int i = 0; i < 3; i++) {
        int idx = lane + 32 * i;
        float4 s4 = sh4[idx], m4 = sc4[idx];
        float y0 = (v[i].x - mean) * rstd * (1.f + m4.x) + s4.x;
        float y1 = (v[i].y - mean) * rstd * (1.f + m4.y) + s4.y;
        float y2 = (v[i].z - mean) * rstd * (1.f + m4.z) + s4.z;
        float y3 = (v[i].w - mean) * rstd * (1.f + m4.w) + s4.w;
        orow[idx * 2]     = packbf(y0, y1);
        orow[idx * 2 + 1] = packbf(y2, y3);
    }
}

// ---------------------------------------------------------------------------
// bf16 GEMM: C[M,N] = A[M,K] @ W[N,K]^T (+bias) + epilogue.
// Block 128x128, BK=32 elems (16 u32). 256 threads = 8 warps, warp tile 64x32
// (warp grid 2 M x 4 N). ldmatrix.x4 fragment loads, double-buffered cp.async.
// MODE 0: bias -> bf16   MODE 1: gelu -> bf16   MODE 2: res+gate -> fp32
// ---------------------------------------------------------------------------
#define SOFF(buf, r, k) ((buf) * (128 * 20) + (r) * 20 + (k))

template <int MODE>
__global__ __launch_bounds__(256) void gemm_bf(
    const uint32_t* __restrict__ A, const uint32_t* __restrict__ Bw,
    const float* __restrict__ bias, void* __restrict__ Cout,
    int M, int N, int K2,
    const float* __restrict__ res, int gateOff)
{
    __shared__ uint32_t As[2 * 128 * 20];
    __shared__ uint32_t Bs[2 * 128 * 20];

    int tid  = threadIdx.x;
    int warp = tid >> 5, lane = tid & 31;
    int g = lane >> 2, c = lane & 3;
    int wm = (warp & 1) * 64;        // 2 warps over M
    int wn = (warp >> 1) * 32;       // 4 warps over N
    int bm = blockIdx.y * 128;
    int bn = blockIdx.x * 128;

    // ldmatrix lane address components
    int a_row = (lane & 15);             // within 16-row tile
    int a_ko  = (lane >> 4) * 4;         // +0 or +4 u32
    int b_row = (lane & 7) + ((lane >> 4) & 1) * 8;  // two n8 tiles
    int b_ko  = ((lane >> 3) & 1) * 4;

    float acc[4][4][4];
#pragma unroll
    for (int i = 0; i < 4; i++)
#pragma unroll
        for (int j = 0; j < 4; j++)
#pragma unroll
            for (int t = 0; t < 4; t++) acc[i][j][t] = 0.f;

    int nk = K2 >> 4;

    // stage tile 0: 2048 u32 per array, 256 threads x 2 float4 each
#pragma unroll
    for (int i = 0; i < 2; i++) {
        int idx = tid + 256 * i;
        int row = idx >> 2, c4 = (idx & 3) << 2;
        cp16(&As[SOFF(0, row, c4)], A  + (size_t)(bm + row) * K2 + c4);
        cp16(&Bs[SOFF(0, row, c4)], Bw + (size_t)(bn + row) * K2 + c4);
    }
    asm volatile("cp.async.commit_group;");

    for (int kt = 0; kt < nk; kt++) {
        int buf = kt & 1;
        if (kt + 1 < nk) {
            int k0 = (kt + 1) << 4;
#pragma unroll
            for (int i = 0; i < 2; i++) {
                int idx = tid + 256 * i;
                int row = idx >> 2, c4 = (idx & 3) << 2;
                cp16(&As[SOFF(buf ^ 1, row, c4)], A  + (size_t)(bm + row) * K2 + k0 + c4);
                cp16(&Bs[SOFF(buf ^ 1, row, c4)], Bw + (size_t)(bn + row) * K2 + k0 + c4);
            }
            asm volatile("cp.async.commit_group;");
            asm volatile("cp.async.wait_group 1;");
        } else {
            asm volatile("cp.async.wait_group 0;");
        }
        __syncthreads();

#pragma unroll
        for (int ks = 0; ks < 2; ks++) {   // two k16 steps per BK=32
            int kb = ks << 3;
            uint32_t af[4][4];
#pragma unroll
            for (int mt = 0; mt < 4; mt++)
                ldsm4(af[mt], &As[SOFF(buf, wm + mt * 16 + a_row, kb + a_ko)]);
            uint32_t bfr[2][4];
#pragma unroll
            for (int p = 0; p < 2; p++)
                ldsm4(bfr[p], &Bs[SOFF(buf, wn + p * 16 + b_row, kb + b_ko)]);
#pragma unroll
            for (int mt = 0; mt < 4; mt++) {
#pragma unroll
                for (int nt = 0; nt < 4; nt++)
                    mmabf(acc[mt][nt], af[mt], &bfr[nt >> 1][(nt & 1) * 2]);
            }
        }
        __syncthreads();
    }

    // epilogue
#pragma unroll
    for (int mt = 0; mt < 4; mt++) {
        int r0 = bm + wm + mt * 16 + g;
#pragma unroll
        for (int nt = 0; nt < 4; nt++) {
            int col = bn + wn + nt * 8 + (c << 1);
            float b0 = bias[col], b1 = bias[col + 1];
#pragma unroll
            for (int half = 0; half < 2; half++) {
                int row = r0 + half * 8;
                float v0 = acc[mt][nt][half * 2 + 0] + b0;
                float v1 = acc[mt][nt][half * 2 + 1] + b1;
                if (MODE == 1) {
                    v0 = 0.5f * v0 * (1.f + erff(v0 * 0.7071067811865476f));
                    v1 = 0.5f * v1 * (1.f + erff(v1 * 0.7071067811865476f));
                }
                if (MODE == 2) {
                    int bb = row >> 14;
                    float g0 = g_params[bb * SIXC + gateOff + col];
                    float g1 = g_params[bb * SIXC + gateOff + col + 1];
                    const float2 rr = *(const float2*)(res + (size_t)row * N + col);
                    *(float2*)((float*)Cout + (size_t)row * N + col) =
                        make_float2(rr.x + g0 * v0, rr.y + g1 * v1);
                } else {
                    ((uint32_t*)Cout)[(size_t)row * (N >> 1) + (col >> 1)] = packbf(v0, v1);
                }
            }
        }
    }
}

// ---------------------------------------------------------------------------
// Windowed attention, bf16 mma. Block = (window, head), 128 threads = 4 warps.
// ---------------------------------------------------------------------------
__global__ __launch_bounds__(128) void attn_kernel(
    const uint32_t* __restrict__ qkv, uint32_t* __restrict__ attn_out)
{
    __shared__ uint32_t Qs[64 * 20];
    __shared__ uint32_t Ks[64 * 20];
    __shared__ __nv_bfloat16 Vt[32 * 72];

    int tid = threadIdx.x;
    int warp = tid >> 5, lane = tid & 31;
    int g = lane >> 2, c = lane & 3;
    int win  = blockIdx.x / HEADS_;
    int head = blockIdx.x % HEADS_;

    int b = win >> 8, rem = win & 255;
    int hb = rem >> 5, rem2 = rem & 31, wb = rem2 >> 2, db = rem2 & 3;
    int base = b * 16384 + hb * 4 * 512 + wb * 4 * 16 + db * 4;

    for (int idx = tid; idx < 1024; idx += 128) {
        int r = idx >> 4, cc = idx & 15;
        int tok = base + (r >> 4) * 512 + ((r >> 2) & 3) * 16 + (r & 3);
        const uint32_t* p = qkv + (size_t)tok * 576 + head * 16 + cc;
        Qs[r * 20 + cc] = p[0];
        Ks[r * 20 + cc] = p[192];
    }
    const __nv_bfloat16* qkvh = (const __nv_bfloat16*)qkv;
    for (int idx = tid; idx < 2048; idx += 128) {
        int r = idx >> 5, hd = idx & 31;
        int tok = base + (r >> 4) * 512 + ((r >> 2) & 3) * 16 + (r & 3);
        Vt[hd * 72 + r] = qkvh[(size_t)tok * 1152 + 768 + head * 32 + hd];
    }
    __syncthreads();

    float sacc[8][4];
#pragma unroll
    for (int i = 0; i < 8; i++)
#pragma unroll
        for (int t = 0; t < 4; t++) sacc[i][t] = 0.f;

    int r0 = warp * 16;
#pragma unroll
    for (int ks = 0; ks < 2; ks++) {
        int kb = ks << 3;
        uint32_t af[4];
        af[0] = Qs[(r0 + g) * 20 + kb + c];
        af[1] = Qs[(r0 + g + 8) * 20 + kb + c];
        af[2] = Qs[(r0 + g) * 20 + kb + c + 4];
        af[3] = Qs[(r0 + g + 8) * 20 + kb + c + 4];
#pragma unroll
        for (int nt = 0; nt < 8; nt++) {
            uint32_t bfr[2];
            bfr[0] = Ks[(nt * 8 + g) * 20 + kb + c];
            bfr[1] = Ks[(nt * 8 + g) * 20 + kb + c + 4];
            mmabf(sacc[nt], af, bfr);
        }
    }

    const float SC = 0.17677669529663687f;
    float slo = 0.f, shi = 0.f;
#pragma unroll
    for (int nt = 0; nt < 8; nt++) {
        sacc[nt][0] = __expf(sacc[nt][0] * SC);
        sacc[nt][1] = __expf(sacc[nt][1] * SC);
        sacc[nt][2] = __expf(sacc[nt][2] * SC);
        sacc[nt][3] = __expf(sacc[nt][3] * SC);
        slo += sacc[nt][0] + sacc[nt][1];
        shi += sacc[nt][2] + sacc[nt][3];
    }
    slo += __shfl_xor_sync(0xffffffffu, slo, 1);
    slo += __shfl_xor_sync(0xffffffffu, slo, 2);
    shi += __shfl_xor_sync(0xffffffffu, shi, 1);
    shi += __shfl_xor_sync(0xffffffffu, shi, 2);

    float o[4][4];
#pragma unroll
    for (int i = 0; i < 4; i++)
#pragma unroll
        for (int t = 0; t < 4; t++) o[i][t] = 0.f;

    const uint32_t* Vt32 = (const uint32_t*)Vt;
#pragma unroll
    for (int kt = 0; kt < 4; kt++) {
        uint32_t pa[4];
        pa[0] = packbf(sacc[2 * kt][0],     sacc[2 * kt][1]);
        pa[1] = packbf(sacc[2 * kt][2],     sacc[2 * kt][3]);
        pa[2] = packbf(sacc[2 * kt + 1][0], sacc[2 * kt + 1][1]);
        pa[3] = packbf(sacc[2 * kt + 1][2], sacc[2 * kt + 1][3]);
#pragma unroll
        for (int nt = 0; nt < 4; nt++) {
            uint32_t bfr[2];
            const uint32_t* vrow = Vt32 + (nt * 8 + g) * 36;
            bfr[0] = vrow[kt * 8 + c];
            bfr[1] = vrow[kt * 8 + c + 4];
            mmabf(o[nt], pa, bfr);
        }
    }

    float inv_lo = 1.f / slo, inv_hi = 1.f / shi;
#pragma unroll
    for (int half = 0; half < 2; half++) {
        int r = r0 + g + half * 8;
        int tok = base + (r >> 4) * 512 + ((r >> 2) & 3) * 16 + (r & 3);
        uint32_t* op = attn_out + (size_t)tok * 192 + head * 16;
        float inv = half ? inv_hi : inv_lo;
#pragma unroll
        for (int nt = 0; nt < 4; nt++)
            op[nt * 4 + c] = packbf(o[nt][half * 2] * inv, o[nt][half * 2 + 1] * inv);
    }
}

// ---------------------------------------------------------------------------
// launch
// ---------------------------------------------------------------------------
extern "C" void kernel_launch(void* const* d_in, const int* in_sizes, int n_in,
                              void* d_out, int out_size)
{
    const float* x      = (const float*)d_in[0];
    const float* xn     = (const float*)d_in[1];
    const float* ada_w  = (const float*)d_in[2];
    const float* ada_b  = (const float*)d_in[3];
    const float* qkv_w  = (const float*)d_in[4];
    const float* qkv_b  = (const float*)d_in[5];
    const float* out_w  = (const float*)d_in[6];
    const float* out_b  = (const float*)d_in[7];
    const float* mlp_w1 = (const float*)d_in[8];
    const float* mlp_b1 = (const float*)d_in[9];
    const float* mlp_w2 = (const float*)d_in[10];
    const float* mlp_b2 = (const float*)d_in[11];
    float* out = (float*)d_out;

    void *p_xmod, *p_qkv, *p_attn, *p_x1, *p_h, *p_wq, *p_wo, *p_w1, *p_w2;
    cudaGetSymbolAddress(&p_xmod, g_xmod);
    cudaGetSymbolAddress(&p_qkv,  g_qkv);
    cudaGetSymbolAddress(&p_attn, g_attn);
    cudaGetSymbolAddress(&p_x1,   g_x1);
    cudaGetSymbolAddress(&p_h,    g_h);
    cudaGetSymbolAddress(&p_wq,   g_wq);
    cudaGetSymbolAddress(&p_wo,   g_wo);
    cudaGetSymbolAddress(&p_w1,   g_w1);
    cudaGetSymbolAddress(&p_w2,   g_w2);

    cvt_kernel<<<(NWQ + NWO + NW1 + NW2) / 256, 256>>>(qkv_w, out_w, mlp_w1, mlp_w2);
    ada_kernel<<<18, 256>>>(xn, ada_w, ada_b);
    ln_mod_kernel<<<TOK / 8, 256>>>(x, 0, C_, (uint32_t*)p_xmod);

    {
        dim3 grid((3 * C_) / 128, TOK / 128);
        gemm_bf<0><<<grid, 256>>>((const uint32_t*)p_xmod, (const uint32_t*)p_wq,
                                  qkv_b, p_qkv, TOK, 3 * C_, C_ / 2, nullptr, 0);
    }

    attn_kernel<<<NWIN * HEADS_, 128>>>((const uint32_t*)p_qkv, (uint32_t*)p_attn);

    {
        dim3 grid(C_ / 128, TOK / 128);
        gemm_bf<2><<<grid, 256>>>((const uint32_t*)p_attn, (const uint32_t*)p_wo,
                                  out_b, p_x1, TOK, C_, C_ / 2, x, 2 * C_);
    }

    ln_mod_kernel<<<TOK / 8, 256>>>((const float*)p_x1, 3 * C_, 4 * C_, (uint32_t*)p_xmod);

    {
        dim3 grid((4 * C_) / 128, TOK / 128);
        gemm_bf<1><<<grid, 256>>>((const uint32_t*)p_xmod, (const uint32_t*)p_w1,
                                  mlp_b1, p_h, TOK, 4 * C_, C_ / 2, nullptr, 0);
    }

    {
        dim3 grid(C_ / 128, TOK / 128);
        gemm_bf<2><<<grid, 256>>>((const uint32_t*)p_h, (const uint32_t*)p_w2,
                                  mlp_b2, out, TOK, C_, 2 * C_, (const float*)p_x1, 5 * C_);
    }
}